// round 15
// baseline (speedup 1.0000x reference)
#include <cuda_runtime.h>
#include <math.h>

// Problem constants
#define Vv 32000
#define Ee 512
#define Hh 512
#define G4 2048   // 4*H
#define Bb 64
#define Tt 256
#define GRID 128  // persistent CTAs, 1/SM -> all co-resident
#define NT 256

typedef unsigned long long ull;

// ---------------- device scratch ----------------
__device__ float g_WT_fc[(size_t)Ee * Vv];   // [k][v] transposed W_fc
__device__ float g_h[2][2][Hh * Bb];         // [ping][layer][unit*64+b]
__device__ ull   g_amax[Bb];                 // packed (orderable float | ~idx)
__device__ unsigned g_bar_count;
__device__ volatile unsigned g_bar_gen;

// ---------------- packed f32x2 FMA helpers ----------------
__device__ __forceinline__ void ffma2(ull& d, ull a, ull b) {
    asm("fma.rn.f32x2 %0, %1, %2, %0;" : "+l"(d) : "l"(a), "l"(b));
}
__device__ __forceinline__ ull pack2(float v) {
    ull r; asm("mov.b64 %0, {%1, %1};" : "=l"(r) : "f"(v)); return r;
}
__device__ __forceinline__ float2 unpack2(ull a) {
    float2 r; asm("mov.b64 {%0, %1}, %2;" : "=f"(r.x), "=f"(r.y) : "l"(a)); return r;
}
__device__ __forceinline__ ull amax_pack(float f, int idx) {
    unsigned b = __float_as_uint(f);
    unsigned key = (b & 0x80000000u) ? ~b : (b | 0x80000000u);
    return ((ull)key << 32) | (ull)(0xFFFFFFFFu - (unsigned)idx);
}

// ---------------- grid-wide barrier ----------------
__device__ __forceinline__ void gsync() {
    __threadfence();
    __syncthreads();
    if (threadIdx.x == 0) {
        unsigned gen = g_bar_gen;
        unsigned t = atomicAdd(&g_bar_count, 1u);
        if (t == GRID - 1) {
            g_bar_count = 0;
            __threadfence();
            g_bar_gen = gen + 1;
        } else {
            while (g_bar_gen == gen) { }
        }
    }
    __syncthreads();
}

// smem map (floats): [0, 32768) gate weights; [32768, 49152) stage/scratch (64 KB)
#define STG_OFF 32768

// ---------------- LSTM layer (R14-proven) ----------------
// warp w = (m = w>>2: 0 ih / 1 hh, ks = w&3: k-quarter within each 32-k chunk)
// lane: jg = lane>>4 (unit pair), bq = lane&15 (4 batches)
// Acts staged in 32-k double-buffered smem chunks (each element read once/CTA).
// If inp == nullptr, layer input is gathered from emb rows via s_tok (layer 0).
__device__ __forceinline__ void lstm_layer(
    float* wsm, int layer,
    const float* __restrict__ inp,
    const float* __restrict__ emb, const int* __restrict__ s_tok,
    const float* __restrict__ hin, float* __restrict__ hout, float& creg,
    const float* __restrict__ bih, const float* __restrict__ bhh,
    int cta, int tid)
{
    float* stg = wsm + STG_OFF;          // 2 bufs x (2 matrices x 2048 floats)
    int w = tid >> 5, lane = tid & 31;
    int m = w >> 2, ks = w & 3;
    int jg = lane >> 4, bq = lane & 15;
    int gb = tid >> 2, kq = tid & 3;     // gather roles (m0, layer0)

    ull acc[16];
    #pragma unroll
    for (int i = 0; i < 16; i++) acc[i] = 0ull;

    const float4* h4 = (const float4*)hin;
    const float4* i4 = (const float4*)inp;

    // stage chunk 0
    {
        float4 p0 = __ldcg(h4 + tid * 2), p1 = __ldcg(h4 + tid * 2 + 1);
        *(float4*)&stg[2048 + tid * 8]     = p0;
        *(float4*)&stg[2048 + tid * 8 + 4] = p1;
        if (inp) {
            float4 q0 = __ldcg(i4 + tid * 2), q1 = __ldcg(i4 + tid * 2 + 1);
            *(float4*)&stg[tid * 8]     = q0;
            *(float4*)&stg[tid * 8 + 4] = q1;
        } else {
            const float* er = emb + (size_t)s_tok[gb] * Ee + kq * 8;
            float4 q0 = __ldcg((const float4*)er), q1 = __ldcg((const float4*)er + 1);
            stg[(kq * 8 + 0) * 64 + gb] = q0.x; stg[(kq * 8 + 1) * 64 + gb] = q0.y;
            stg[(kq * 8 + 2) * 64 + gb] = q0.z; stg[(kq * 8 + 3) * 64 + gb] = q0.w;
            stg[(kq * 8 + 4) * 64 + gb] = q1.x; stg[(kq * 8 + 5) * 64 + gb] = q1.y;
            stg[(kq * 8 + 6) * 64 + gb] = q1.z; stg[(kq * 8 + 7) * 64 + gb] = q1.w;
        }
    }
    __syncthreads();

    const float* w0p = wsm + (unsigned)(layer * 8 + m * 4 + jg * 2) * 2048;
    const float* w1p = w0p + 2048;

    int d = 0;
    #pragma unroll 1
    for (int c = 0; c < 16; c++) {
        // prefetch chunk c+1
        float4 p0, p1, q0, q1;
        if (c < 15) {
            p0 = __ldcg(h4 + (c + 1) * 512 + tid * 2);
            p1 = __ldcg(h4 + (c + 1) * 512 + tid * 2 + 1);
            if (inp) {
                q0 = __ldcg(i4 + (c + 1) * 512 + tid * 2);
                q1 = __ldcg(i4 + (c + 1) * 512 + tid * 2 + 1);
            } else {
                const float* er = emb + (size_t)s_tok[gb] * Ee + (c + 1) * 32 + kq * 8;
                q0 = __ldcg((const float4*)er);
                q1 = __ldcg((const float4*)er + 1);
            }
        }
        // compute chunk c: this warp handles k_in = ks*8 .. ks*8+7
        const float* ab = stg + d * 4096 + m * 2048 + bq * 4;
        #pragma unroll
        for (int i = 0; i < 8; i++) {
            int kin = ks * 8 + i;
            int kg4 = (c * 32 + kin) * 4;
            float4 w0 = *(const float4*)(w0p + kg4);
            float4 w1 = *(const float4*)(w1p + kg4);
            ulonglong2 av = *(const ulonglong2*)(ab + kin * 64);
            ffma2(acc[0],  av.x, pack2(w0.x)); ffma2(acc[1],  av.y, pack2(w0.x));
            ffma2(acc[2],  av.x, pack2(w0.y)); ffma2(acc[3],  av.y, pack2(w0.y));
            ffma2(acc[4],  av.x, pack2(w0.z)); ffma2(acc[5],  av.y, pack2(w0.z));
            ffma2(acc[6],  av.x, pack2(w0.w)); ffma2(acc[7],  av.y, pack2(w0.w));
            ffma2(acc[8],  av.x, pack2(w1.x)); ffma2(acc[9],  av.y, pack2(w1.x));
            ffma2(acc[10], av.x, pack2(w1.y)); ffma2(acc[11], av.y, pack2(w1.y));
            ffma2(acc[12], av.x, pack2(w1.z)); ffma2(acc[13], av.y, pack2(w1.z));
            ffma2(acc[14], av.x, pack2(w1.w)); ffma2(acc[15], av.y, pack2(w1.w));
        }
        if (c < 15) {
            float* nb = stg + (d ^ 1) * 4096;
            *(float4*)&nb[2048 + tid * 8]     = p0;
            *(float4*)&nb[2048 + tid * 8 + 4] = p1;
            if (inp) {
                *(float4*)&nb[tid * 8]     = q0;
                *(float4*)&nb[tid * 8 + 4] = q1;
            } else {
                nb[(kq * 8 + 0) * 64 + gb] = q0.x; nb[(kq * 8 + 1) * 64 + gb] = q0.y;
                nb[(kq * 8 + 2) * 64 + gb] = q0.z; nb[(kq * 8 + 3) * 64 + gb] = q0.w;
                nb[(kq * 8 + 4) * 64 + gb] = q1.x; nb[(kq * 8 + 5) * 64 + gb] = q1.y;
                nb[(kq * 8 + 6) * 64 + gb] = q1.z; nb[(kq * 8 + 7) * 64 + gb] = q1.w;
            }
        }
        __syncthreads();
        d ^= 1;
    }

    // reduction: 8 partials (2m x 4ks) per output
    ull* sred = (ull*)(wsm + STG_OFF);   // 4096 ull = 32 KB
    #pragma unroll
    for (int i = 0; i < 16; i++) sred[tid * 16 + i] = acc[i];
    __syncthreads();

    {
        int u = tid >> 6, b = tid & 63;
        int jgc = u >> 1, uu = u & 1;
        int bqc = b >> 2, bp = (b >> 1) & 1, be = b & 1;
        int lanec = jgc * 16 + bqc;
        float gate[4];
        #pragma unroll
        for (int g = 0; g < 4; g++) {
            float s = 0.0f;
            #pragma unroll
            for (int ww = 0; ww < 8; ww++) {
                float2 p = unpack2(sred[(ww * 32 + lanec) * 16 + uu * 8 + g * 2 + bp]);
                s += be ? p.y : p.x;
            }
            gate[g] = s;
        }
        int j0 = cta * 4 + u;
        float iv = gate[0] + bih[j0]        + bhh[j0];
        float fv = gate[1] + bih[512 + j0]  + bhh[512 + j0];
        float gv = gate[2] + bih[1024 + j0] + bhh[1024 + j0];
        float ov = gate[3] + bih[1536 + j0] + bhh[1536 + j0];
        float ig = 1.0f / (1.0f + expf(-iv));
        float fg = 1.0f / (1.0f + expf(-fv));
        float og = 1.0f / (1.0f + expf(-ov));
        float cn = fg * creg + ig * tanhf(gv);
        float hn = og * tanhf(cn);
        creg = cn;
        __stcg(&hout[j0 * Bb + b], hn);
    }
    __syncthreads();
}

// ---------------- single persistent kernel ----------------
__global__ void __launch_bounds__(NT, 1)
kmain(const int* __restrict__ x, const float* __restrict__ emb,
      const float* __restrict__ W_ih, const float* __restrict__ W_hh,
      const float* __restrict__ b_ih, const float* __restrict__ b_hh,
      const float* __restrict__ W_fc, const float* __restrict__ bfc,
      float* __restrict__ out)
{
    extern __shared__ float wsm[];
    __shared__ int s_tok[64];

    int tid = threadIdx.x;
    int cta = blockIdx.x;

    // ================= per-replay init =================
    ((float2*)&g_h[0][0][0])[cta * 256 + tid] = make_float2(0.0f, 0.0f);
    if (cta == 0 && tid < Bb)
        g_amax[tid] = amax_pack(0.0f, x[tid * Tt]);   // seed step-0 tokens

    // gate weights -> smem: row r = layer*8 + m*4 + u; wsm[r][k] = (wi,wf,wg,wo)
    #pragma unroll 1
    for (int r = 0; r < 16; r++) {
        int l = r >> 3, m = (r >> 2) & 1, u = r & 3;
        const float* base = (m ? W_hh : W_ih) + (size_t)l * G4 * 512
                            + (size_t)(cta * 4 + u) * 512;
        #pragma unroll
        for (int half = 0; half < 2; half++) {
            int k = tid + half * 256;
            float4 wv;
            wv.x = base[k];
            wv.y = base[(size_t)512 * 512 + k];
            wv.z = base[(size_t)1024 * 512 + k];
            wv.w = base[(size_t)1536 * 512 + k];
            *(float4*)&wsm[r * 2048 + k * 4] = wv;
        }
    }
    // transpose W_fc -> g_WT_fc [k][v]: each CTA owns 250 vocab rows
    if (tid < 250) {
        int v = cta * 250 + tid;
        const float4* src = (const float4*)(W_fc + (size_t)v * Ee);
        #pragma unroll 4
        for (int kq = 0; kq < 128; kq++) {
            float4 r = src[kq];
            size_t k = (size_t)kq * 4;
            g_WT_fc[k * Vv + v]       = r.x;
            g_WT_fc[(k + 1) * Vv + v] = r.y;
            g_WT_fc[(k + 2) * Vv + v] = r.z;
            g_WT_fc[(k + 3) * Vv + v] = r.w;
        }
    }

    float creg0 = 0.0f, creg1 = 0.0f;
    gsync();

    // ================= timestep loop =================
    for (int t = 0; t < Tt; t++) {
        int pi = t & 1, po = pi ^ 1;

        // decode this step's tokens (argmax of previous step / seeded x0)
        if (tid < 64) {
            ull pv = __ldcg((const ull*)&g_amax[tid]);
            s_tok[tid] = (int)(0xFFFFFFFFu - (unsigned)(pv & 0xFFFFFFFFull));
        }
        __syncthreads();

        // ---- layer 0 (input gathered from emb rows)
        lstm_layer(wsm, 0, (const float*)0, emb, s_tok,
                   &g_h[pi][0][0], &g_h[po][0][0], creg0,
                   b_ih, b_hh, cta, tid);
        gsync();

        // reset amax for the upcoming FC (everyone has read tokens by now)
        if (cta == 0 && tid < Bb) g_amax[tid] = 0ull;

        // ---- layer 1 (input = fresh layer-0 h)
        lstm_layer(wsm, 1, &g_h[po][0][0], emb, s_tok,
                   &g_h[pi][1][0], &g_h[po][1][0], creg1,
                   b_ih + G4, b_hh + G4, cta, tid);
        gsync();

        // ---- FC head: 2-way k-split, thread tile 16 vocab x 8 batch ----
        if (cta < 125) {
            int grp = tid >> 7, g = tid & 127;
            int vg = g & 15, bq = g >> 4;
            int v0 = cta * 256 + vg * 16;
            int b0 = bq * 8;
            int k0 = grp * 256;
            const float* hbase = &g_h[po][1][0];
            const float* Wb = g_WT_fc + v0;

            ull acc[16][4];
            #pragma unroll
            for (int v = 0; v < 16; v++) {
                acc[v][0] = 0; acc[v][1] = 0; acc[v][2] = 0; acc[v][3] = 0;
            }

            float wA[16], wB[16];
            ulonglong2 aA[2], aB[2];

#define FCLOAD(W, A, kk) { \
    const float4* wr = (const float4*)(Wb + (size_t)(kk) * Vv); \
    float4 x0 = wr[0], x1 = wr[1], x2 = wr[2], x3 = wr[3]; \
    W[0] = x0.x; W[1] = x0.y; W[2]  = x0.z; W[3]  = x0.w; \
    W[4] = x1.x; W[5] = x1.y; W[6]  = x1.z; W[7]  = x1.w; \
    W[8] = x2.x; W[9] = x2.y; W[10] = x2.z; W[11] = x2.w; \
    W[12] = x3.x; W[13] = x3.y; W[14] = x3.z; W[15] = x3.w; \
    const ulonglong2* ar = (const ulonglong2*)(hbase + (size_t)(kk) * Bb + b0); \
    A[0] = __ldcg(ar); A[1] = __ldcg(ar + 1); }

#define FCCOMP(W, A) { \
    ull ap0 = A[0].x, ap1 = A[0].y, ap2 = A[1].x, ap3 = A[1].y; \
    _Pragma("unroll") \
    for (int v = 0; v < 16; v++) { \
        ull wp = pack2(W[v]); \
        ffma2(acc[v][0], ap0, wp); \
        ffma2(acc[v][1], ap1, wp); \
        ffma2(acc[v][2], ap2, wp); \
        ffma2(acc[v][3], ap3, wp); } }

            FCLOAD(wA, aA, k0);
            #pragma unroll 1
            for (int k = k0; k < k0 + 256; k += 2) {
                int k1 = (k + 1 < k0 + 256) ? k + 1 : k0;
                FCLOAD(wB, aB, k1);
                FCCOMP(wA, aA);
                int k2 = (k + 2 < k0 + 256) ? k + 2 : k0;
                FCLOAD(wA, aA, k2);
                FCCOMP(wB, aB);
            }
#undef FCLOAD
#undef FCCOMP

            // combine k-halves through smem
            ull* sred = (ull*)(wsm + STG_OFF);     // 8192 ull = 64 KB
            if (grp == 1) {
                #pragma unroll
                for (int v = 0; v < 16; v++)
                    #pragma unroll
                    for (int p = 0; p < 4; p++)
                        sred[g * 64 + v * 4 + p] = acc[v][p];
            }
            __syncthreads();

            if (grp == 0) {
                float bias[16];
                {
                    const float4* bp4 = (const float4*)(bfc + v0);
                    #pragma unroll
                    for (int j = 0; j < 4; j++) {
                        float4 bv = bp4[j];
                        bias[j * 4] = bv.x; bias[j * 4 + 1] = bv.y;
                        bias[j * 4 + 2] = bv.z; bias[j * 4 + 3] = bv.w;
                    }
                }
                #pragma unroll
                for (int bb = 0; bb < 8; bb++) {
                    int p = bb >> 1, hi = bb & 1;
                    int b = b0 + bb;
                    float vals[16];
                    #pragma unroll
                    for (int v = 0; v < 16; v++) {
                        float2 t0 = unpack2(acc[v][p]);
                        float2 t1 = unpack2(sred[g * 64 + v * 4 + p]);
                        float lo = t0.x + t1.x, hiv = t0.y + t1.y;
                        vals[v] = (hi ? hiv : lo) + bias[v];
                    }
                    if (t == Tt - 1) {
                        float* op = out + (size_t)b * Vv + v0;
                        *(float4*)op =
                            make_float4(vals[0], vals[1], vals[2], vals[3]);
                        *(float4*)(op + 4) =
                            make_float4(vals[4], vals[5], vals[6], vals[7]);
                        *(float4*)(op + 8) =
                            make_float4(vals[8], vals[9], vals[10], vals[11]);
                        *(float4*)(op + 12) =
                            make_float4(vals[12], vals[13], vals[14], vals[15]);
                    } else {
                        float mv = vals[0]; int mi = v0;
                        #pragma unroll
                        for (int v = 1; v < 16; v++)
                            if (vals[v] > mv) { mv = vals[v]; mi = v0 + v; }
                        #pragma unroll
                        for (int o = 8; o > 0; o >>= 1) {
                            float ovv = __shfl_down_sync(0xffffffffu, mv, o, 16);
                            int   oii = __shfl_down_sync(0xffffffffu, mi, o, 16);
                            if (ovv > mv || (ovv == mv && oii < mi)) { mv = ovv; mi = oii; }
                        }
                        if (vg == 0) atomicMax(&g_amax[b], amax_pack(mv, mi));
                    }
                }
            }
            __syncthreads();
        }
        gsync();
    }
}

// ---------------- host driver ----------------
extern "C" void kernel_launch(void* const* d_in, const int* in_sizes, int n_in,
                              void* d_out, int out_size) {
    const int*   x    = (const int*)d_in[0];
    const float* emb  = (const float*)d_in[1];
    const float* W_ih = (const float*)d_in[2];
    const float* W_hh = (const float*)d_in[3];
    const float* b_ih = (const float*)d_in[4];
    const float* b_hh = (const float*)d_in[5];
    const float* W_fc = (const float*)d_in[6];
    const float* b_fc = (const float*)d_in[7];
    float* out = (float*)d_out;

    const int SMEM = (32768 + 16384) * (int)sizeof(float);   // 192 KB
    cudaFuncSetAttribute(kmain, cudaFuncAttributeMaxDynamicSharedMemorySize, SMEM);

    kmain<<<GRID, NT, SMEM>>>(x, emb, W_ih, W_hh, b_ih, b_hh, W_fc, b_fc, out);
}

// round 16
// speedup vs baseline: 1.3021x; 1.3021x over previous
#include <cuda_runtime.h>
#include <math.h>

// Problem constants
#define Vv 32000
#define Ee 512
#define Hh 512
#define G4 2048   // 4*H
#define Bb 64
#define Tt 256
#define GRID 128  // persistent CTAs, 1/SM -> all co-resident
#define NT 256

typedef unsigned long long ull;

// ---------------- device scratch ----------------
__device__ float g_WT_fc[(size_t)Ee * Vv];   // [k][v] transposed W_fc
__device__ float g_h[2][2][Hh * Bb];         // [ping][layer][unit*64+b]
__device__ ull   g_amax[Bb];                 // packed (orderable float | ~idx)
__device__ unsigned g_bar_count;
__device__ volatile unsigned g_bar_gen;

// ---------------- packed f32x2 FMA helpers ----------------
__device__ __forceinline__ void ffma2(ull& d, ull a, ull b) {
    asm("fma.rn.f32x2 %0, %1, %2, %0;" : "+l"(d) : "l"(a), "l"(b));
}
__device__ __forceinline__ ull pack2(float v) {
    ull r; asm("mov.b64 %0, {%1, %1};" : "=l"(r) : "f"(v)); return r;
}
__device__ __forceinline__ float2 unpack2(ull a) {
    float2 r; asm("mov.b64 {%0, %1}, %2;" : "=f"(r.x), "=f"(r.y) : "l"(a)); return r;
}
__device__ __forceinline__ ull amax_pack(float f, int idx) {
    unsigned b = __float_as_uint(f);
    unsigned key = (b & 0x80000000u) ? ~b : (b | 0x80000000u);
    return ((ull)key << 32) | (ull)(0xFFFFFFFFu - (unsigned)idx);
}

// ---------------- grid-wide barrier ----------------
__device__ __forceinline__ void gsync() {
    __threadfence();
    __syncthreads();
    if (threadIdx.x == 0) {
        unsigned gen = g_bar_gen;
        unsigned t = atomicAdd(&g_bar_count, 1u);
        if (t == GRID - 1) {
            g_bar_count = 0;
            __threadfence();
            g_bar_gen = gen + 1;
        } else {
            while (g_bar_gen == gen) { }
        }
    }
    __syncthreads();
}

// smem map (floats): [0, 32768) gate weights; [32768, 41472) stage/scratch
#define STG_OFF 32768
#define FSTRIDE 132     // 16 k x 8 v + 4 pad (conflict-free LDS.128)

// ---------------- LSTM layer (R14-proven, unchanged) ----------------
__device__ __forceinline__ void lstm_layer(
    float* wsm, int layer,
    const float* __restrict__ inp,
    const float* __restrict__ emb, const int* __restrict__ s_tok,
    const float* __restrict__ hin, float* __restrict__ hout, float& creg,
    const float* __restrict__ bih, const float* __restrict__ bhh,
    int cta, int tid)
{
    float* stg = wsm + STG_OFF;          // 2 bufs x (2 matrices x 2048 floats)
    int w = tid >> 5, lane = tid & 31;
    int m = w >> 2, ks = w & 3;
    int jg = lane >> 4, bq = lane & 15;
    int gb = tid >> 2, kq = tid & 3;     // gather roles (m0, layer0)

    ull acc[16];
    #pragma unroll
    for (int i = 0; i < 16; i++) acc[i] = 0ull;

    const float4* h4 = (const float4*)hin;
    const float4* i4 = (const float4*)inp;

    // stage chunk 0
    {
        float4 p0 = __ldcg(h4 + tid * 2), p1 = __ldcg(h4 + tid * 2 + 1);
        *(float4*)&stg[2048 + tid * 8]     = p0;
        *(float4*)&stg[2048 + tid * 8 + 4] = p1;
        if (inp) {
            float4 q0 = __ldcg(i4 + tid * 2), q1 = __ldcg(i4 + tid * 2 + 1);
            *(float4*)&stg[tid * 8]     = q0;
            *(float4*)&stg[tid * 8 + 4] = q1;
        } else {
            const float* er = emb + (size_t)s_tok[gb] * Ee + kq * 8;
            float4 q0 = __ldcg((const float4*)er), q1 = __ldcg((const float4*)er + 1);
            stg[(kq * 8 + 0) * 64 + gb] = q0.x; stg[(kq * 8 + 1) * 64 + gb] = q0.y;
            stg[(kq * 8 + 2) * 64 + gb] = q0.z; stg[(kq * 8 + 3) * 64 + gb] = q0.w;
            stg[(kq * 8 + 4) * 64 + gb] = q1.x; stg[(kq * 8 + 5) * 64 + gb] = q1.y;
            stg[(kq * 8 + 6) * 64 + gb] = q1.z; stg[(kq * 8 + 7) * 64 + gb] = q1.w;
        }
    }
    __syncthreads();

    const float* w0p = wsm + (unsigned)(layer * 8 + m * 4 + jg * 2) * 2048;
    const float* w1p = w0p + 2048;

    int d = 0;
    #pragma unroll 1
    for (int c = 0; c < 16; c++) {
        float4 p0, p1, q0, q1;
        if (c < 15) {
            p0 = __ldcg(h4 + (c + 1) * 512 + tid * 2);
            p1 = __ldcg(h4 + (c + 1) * 512 + tid * 2 + 1);
            if (inp) {
                q0 = __ldcg(i4 + (c + 1) * 512 + tid * 2);
                q1 = __ldcg(i4 + (c + 1) * 512 + tid * 2 + 1);
            } else {
                const float* er = emb + (size_t)s_tok[gb] * Ee + (c + 1) * 32 + kq * 8;
                q0 = __ldcg((const float4*)er);
                q1 = __ldcg((const float4*)er + 1);
            }
        }
        const float* ab = stg + d * 4096 + m * 2048 + bq * 4;
        #pragma unroll
        for (int i = 0; i < 8; i++) {
            int kin = ks * 8 + i;
            int kg4 = (c * 32 + kin) * 4;
            float4 w0 = *(const float4*)(w0p + kg4);
            float4 w1 = *(const float4*)(w1p + kg4);
            ulonglong2 av = *(const ulonglong2*)(ab + kin * 64);
            ffma2(acc[0],  av.x, pack2(w0.x)); ffma2(acc[1],  av.y, pack2(w0.x));
            ffma2(acc[2],  av.x, pack2(w0.y)); ffma2(acc[3],  av.y, pack2(w0.y));
            ffma2(acc[4],  av.x, pack2(w0.z)); ffma2(acc[5],  av.y, pack2(w0.z));
            ffma2(acc[6],  av.x, pack2(w0.w)); ffma2(acc[7],  av.y, pack2(w0.w));
            ffma2(acc[8],  av.x, pack2(w1.x)); ffma2(acc[9],  av.y, pack2(w1.x));
            ffma2(acc[10], av.x, pack2(w1.y)); ffma2(acc[11], av.y, pack2(w1.y));
            ffma2(acc[12], av.x, pack2(w1.z)); ffma2(acc[13], av.y, pack2(w1.z));
            ffma2(acc[14], av.x, pack2(w1.w)); ffma2(acc[15], av.y, pack2(w1.w));
        }
        if (c < 15) {
            float* nb = stg + (d ^ 1) * 4096;
            *(float4*)&nb[2048 + tid * 8]     = p0;
            *(float4*)&nb[2048 + tid * 8 + 4] = p1;
            if (inp) {
                *(float4*)&nb[tid * 8]     = q0;
                *(float4*)&nb[tid * 8 + 4] = q1;
            } else {
                nb[(kq * 8 + 0) * 64 + gb] = q0.x; nb[(kq * 8 + 1) * 64 + gb] = q0.y;
                nb[(kq * 8 + 2) * 64 + gb] = q0.z; nb[(kq * 8 + 3) * 64 + gb] = q0.w;
                nb[(kq * 8 + 4) * 64 + gb] = q1.x; nb[(kq * 8 + 5) * 64 + gb] = q1.y;
                nb[(kq * 8 + 6) * 64 + gb] = q1.z; nb[(kq * 8 + 7) * 64 + gb] = q1.w;
            }
        }
        __syncthreads();
        d ^= 1;
    }

    // reduction: 8 partials (2m x 4ks) per output
    ull* sred = (ull*)(wsm + STG_OFF);
    #pragma unroll
    for (int i = 0; i < 16; i++) sred[tid * 16 + i] = acc[i];
    __syncthreads();

    {
        int u = tid >> 6, b = tid & 63;
        int jgc = u >> 1, uu = u & 1;
        int bqc = b >> 2, bp = (b >> 1) & 1, be = b & 1;
        int lanec = jgc * 16 + bqc;
        float gate[4];
        #pragma unroll
        for (int g = 0; g < 4; g++) {
            float s = 0.0f;
            #pragma unroll
            for (int ww = 0; ww < 8; ww++) {
                float2 p = unpack2(sred[(ww * 32 + lanec) * 16 + uu * 8 + g * 2 + bp]);
                s += be ? p.y : p.x;
            }
            gate[g] = s;
        }
        int j0 = cta * 4 + u;
        float iv = gate[0] + bih[j0]        + bhh[j0];
        float fv = gate[1] + bih[512 + j0]  + bhh[512 + j0];
        float gv = gate[2] + bih[1024 + j0] + bhh[1024 + j0];
        float ov = gate[3] + bih[1536 + j0] + bhh[1536 + j0];
        float ig = 1.0f / (1.0f + expf(-iv));
        float fg = 1.0f / (1.0f + expf(-fv));
        float og = 1.0f / (1.0f + expf(-ov));
        float cn = fg * creg + ig * tanhf(gv);
        float hn = og * tanhf(cn);
        creg = cn;
        __stcg(&hout[j0 * Bb + b], hn);
    }
    __syncthreads();
}

// ---------------- single persistent kernel ----------------
__global__ void __launch_bounds__(NT, 1)
kmain(const int* __restrict__ x, const float* __restrict__ emb,
      const float* __restrict__ W_ih, const float* __restrict__ W_hh,
      const float* __restrict__ b_ih, const float* __restrict__ b_hh,
      const float* __restrict__ W_fc, const float* __restrict__ bfc,
      float* __restrict__ out)
{
    extern __shared__ float wsm[];
    __shared__ int s_tok[64];

    int tid = threadIdx.x;
    int cta = blockIdx.x;

    // ================= per-replay init =================
    ((float2*)&g_h[0][0][0])[cta * 256 + tid] = make_float2(0.0f, 0.0f);
    if (cta == 0 && tid < Bb)
        g_amax[tid] = amax_pack(0.0f, x[tid * Tt]);   // seed step-0 tokens

    // gate weights -> smem
    #pragma unroll 1
    for (int r = 0; r < 16; r++) {
        int l = r >> 3, m = (r >> 2) & 1, u = r & 3;
        const float* base = (m ? W_hh : W_ih) + (size_t)l * G4 * 512
                            + (size_t)(cta * 4 + u) * 512;
        #pragma unroll
        for (int half = 0; half < 2; half++) {
            int k = tid + half * 256;
            float4 wv;
            wv.x = base[k];
            wv.y = base[(size_t)512 * 512 + k];
            wv.z = base[(size_t)1024 * 512 + k];
            wv.w = base[(size_t)1536 * 512 + k];
            *(float4*)&wsm[r * 2048 + k * 4] = wv;
        }
    }
    // transpose W_fc -> g_WT_fc [k][v]
    if (tid < 250) {
        int v = cta * 250 + tid;
        const float4* src = (const float4*)(W_fc + (size_t)v * Ee);
        #pragma unroll 4
        for (int kq = 0; kq < 128; kq++) {
            float4 r = src[kq];
            size_t k = (size_t)kq * 4;
            g_WT_fc[k * Vv + v]       = r.x;
            g_WT_fc[(k + 1) * Vv + v] = r.y;
            g_WT_fc[(k + 2) * Vv + v] = r.z;
            g_WT_fc[(k + 3) * Vv + v] = r.w;
        }
    }

    float creg0 = 0.0f, creg1 = 0.0f;
    gsync();

    // ================= timestep loop =================
    for (int t = 0; t < Tt; t++) {
        int pi = t & 1, po = pi ^ 1;

        // decode this step's tokens
        if (tid < 64) {
            ull pv = __ldcg((const ull*)&g_amax[tid]);
            s_tok[tid] = (int)(0xFFFFFFFFu - (unsigned)(pv & 0xFFFFFFFFull));
        }
        __syncthreads();

        // ---- layer 0 (input gathered from emb rows)
        lstm_layer(wsm, 0, (const float*)0, emb, s_tok,
                   &g_h[pi][0][0], &g_h[po][0][0], creg0,
                   b_ih, b_hh, cta, tid);
        gsync();

        if (cta == 0 && tid < Bb) g_amax[tid] = 0ull;

        // ---- layer 1
        lstm_layer(wsm, 1, &g_h[po][0][0], emb, s_tok,
                   &g_h[pi][1][0], &g_h[po][1][0], creg1,
                   b_ih + G4, b_hh + G4, cta, tid);
        gsync();

        // ---- FC head: 8v x 8b tile, weights via double-buffered smem chunks ----
        if (cta < 125) {
            int bq = tid >> 5, vg = tid & 31;
            int v0 = cta * 256 + vg * 8;
            const float* hb = &g_h[po][1][0] + bq * 8;
            const float* WTc = g_WT_fc + cta * 256;
            float* fsm = wsm + STG_OFF;          // 2 bufs x 32*FSTRIDE floats
            int svg = tid & 31;
            int skr0 = tid >> 5, skr1 = skr0 + 8;

            ull acc[8][4];
            #pragma unroll
            for (int v = 0; v < 8; v++) {
                acc[v][0] = 0; acc[v][1] = 0; acc[v][2] = 0; acc[v][3] = 0;
            }

            // stage chunk 0 (16 k x 256 v) straight into buf 0
            {
                const float4* s0 = (const float4*)(WTc + (size_t)skr0 * Vv + svg * 8);
                const float4* s1 = (const float4*)(WTc + (size_t)skr1 * Vv + svg * 8);
                float4 a0 = __ldcs(s0), a1 = __ldcs(s0 + 1);
                float4 b0 = __ldcs(s1), b1 = __ldcs(s1 + 1);
                *(float4*)&fsm[svg * FSTRIDE + skr0 * 8]     = a0;
                *(float4*)&fsm[svg * FSTRIDE + skr0 * 8 + 4] = a1;
                *(float4*)&fsm[svg * FSTRIDE + skr1 * 8]     = b0;
                *(float4*)&fsm[svg * FSTRIDE + skr1 * 8 + 4] = b1;
            }
            ulonglong2 aA[2], aB[2];
            { const ulonglong2* ar = (const ulonglong2*)hb;
              aA[0] = __ldcg(ar); aA[1] = __ldcg(ar + 1); }
            __syncthreads();

#define LDW(W, base, kk) { \
    const float4* wp4 = (const float4*)((base) + (kk) * 8); \
    float4 w0 = wp4[0], w1 = wp4[1]; \
    W[0] = w0.x; W[1] = w0.y; W[2] = w0.z; W[3] = w0.w; \
    W[4] = w1.x; W[5] = w1.y; W[6] = w1.z; W[7] = w1.w; }

#define FCALOAD(A, kk) { \
    const ulonglong2* ar = (const ulonglong2*)(hb + (size_t)(kk) * Bb); \
    A[0] = __ldcg(ar); A[1] = __ldcg(ar + 1); }

#define FCCOMP(WF, A) { \
    ull ap0 = A[0].x, ap1 = A[0].y, ap2 = A[1].x, ap3 = A[1].y; \
    _Pragma("unroll") \
    for (int v = 0; v < 8; v++) { \
        ull wp = pack2(WF[v]); \
        ffma2(acc[v][0], ap0, wp); \
        ffma2(acc[v][1], ap1, wp); \
        ffma2(acc[v][2], ap2, wp); \
        ffma2(acc[v][3], ap3, wp); } }

            float wbA[8], wbB[8];
            int d = 0;
            #pragma unroll 1
            for (int c = 0; c < 32; c++) {
                // gmem prefetch of chunk c+1 (held in regs until STS below)
                float4 n0, n1, n2, n3;
                if (c < 31) {
                    const float4* s0 = (const float4*)
                        (WTc + (size_t)((c + 1) * 16 + skr0) * Vv + svg * 8);
                    const float4* s1 = (const float4*)
                        (WTc + (size_t)((c + 1) * 16 + skr1) * Vv + svg * 8);
                    n0 = __ldcs(s0); n1 = __ldcs(s0 + 1);
                    n2 = __ldcs(s1); n3 = __ldcs(s1 + 1);
                }
                const float* wcb = fsm + d * (32 * FSTRIDE) + vg * FSTRIDE;
                LDW(wbA, wcb, 0);
                #pragma unroll
                for (int kk = 0; kk < 16; kk += 2) {
                    int kg = c * 16 + kk;
                    int k1 = (kg + 1 < 512) ? kg + 1 : 0;
                    FCALOAD(aB, k1);
                    LDW(wbB, wcb, kk + 1);
                    FCCOMP(wbA, aA);
                    int k2 = (kg + 2 < 512) ? kg + 2 : 0;
                    FCALOAD(aA, k2);
                    if (kk + 2 < 16) LDW(wbA, wcb, kk + 2);
                    FCCOMP(wbB, aB);
                }
                if (c < 31) {
                    float* nb = fsm + (d ^ 1) * (32 * FSTRIDE);
                    *(float4*)&nb[svg * FSTRIDE + skr0 * 8]     = n0;
                    *(float4*)&nb[svg * FSTRIDE + skr0 * 8 + 4] = n1;
                    *(float4*)&nb[svg * FSTRIDE + skr1 * 8]     = n2;
                    *(float4*)&nb[svg * FSTRIDE + skr1 * 8 + 4] = n3;
                }
                __syncthreads();
                d ^= 1;
            }
#undef LDW
#undef FCALOAD
#undef FCCOMP

            float bias[8];
            {
                float4 b0 = *(const float4*)(bfc + v0);
                float4 b1 = *(const float4*)(bfc + v0 + 4);
                bias[0] = b0.x; bias[1] = b0.y; bias[2] = b0.z; bias[3] = b0.w;
                bias[4] = b1.x; bias[5] = b1.y; bias[6] = b1.z; bias[7] = b1.w;
            }
            #pragma unroll
            for (int bb = 0; bb < 8; bb++) {
                int b = bq * 8 + bb;
                float vals[8];
                #pragma unroll
                for (int v = 0; v < 8; v++) {
                    float2 t2 = unpack2(acc[v][bb >> 1]);
                    vals[v] = ((bb & 1) ? t2.y : t2.x) + bias[v];
                }
                if (t == Tt - 1) {
                    *(float4*)(out + (size_t)b * Vv + v0) =
                        make_float4(vals[0], vals[1], vals[2], vals[3]);
                    *(float4*)(out + (size_t)b * Vv + v0 + 4) =
                        make_float4(vals[4], vals[5], vals[6], vals[7]);
                } else {
                    float mv = vals[0]; int mi = v0;
                    #pragma unroll
                    for (int v = 1; v < 8; v++)
                        if (vals[v] > mv) { mv = vals[v]; mi = v0 + v; }
                    #pragma unroll
                    for (int o = 16; o > 0; o >>= 1) {
                        float ovv = __shfl_down_sync(0xffffffffu, mv, o);
                        int   oii = __shfl_down_sync(0xffffffffu, mi, o);
                        if (ovv > mv || (ovv == mv && oii < mi)) { mv = ovv; mi = oii; }
                    }
                    if (vg == 0) atomicMax(&g_amax[b], amax_pack(mv, mi));
                }
            }
        }
        gsync();
    }
}

// ---------------- host driver ----------------
extern "C" void kernel_launch(void* const* d_in, const int* in_sizes, int n_in,
                              void* d_out, int out_size) {
    const int*   x    = (const int*)d_in[0];
    const float* emb  = (const float*)d_in[1];
    const float* W_ih = (const float*)d_in[2];
    const float* W_hh = (const float*)d_in[3];
    const float* b_ih = (const float*)d_in[4];
    const float* b_hh = (const float*)d_in[5];
    const float* W_fc = (const float*)d_in[6];
    const float* b_fc = (const float*)d_in[7];
    float* out = (float*)d_out;

    // 32768 gate weights + 2 x 32*FSTRIDE FC staging = 41216 floats -> pad
    const int SMEM = (32768 + 8704) * (int)sizeof(float);   // 165888 B
    cudaFuncSetAttribute(kmain, cudaFuncAttributeMaxDynamicSharedMemorySize, SMEM);

    kmain<<<GRID, NT, SMEM>>>(x, emb, W_ih, W_hh, b_ih, b_hh, W_fc, b_fc, out);
}